// round 9
// baseline (speedup 1.0000x reference)
#include <cuda_runtime.h>
#include <cstdint>

// LSTMTagger: 262144 sequential steps, H=128, I=2. 4-CTA cluster, 128 thr/CTA.
// R8 = R7 quad scheme with the affine-term bug fixed: x-weights and bias are
// pre-scaled by 0.25 (exact power-of-two) since the quad-reduce sums the
// identical affine contribution from all 4 lanes.
// Quad (4 lanes) owns one h-index, computes ALL 4 gates, k-split-4
// (24 remote + 8 own cols per thread per gate, all in registers).
// shfl.bfly quad-reduce -> every lane has all gate sums -> redundant c/h in
// registers; lane p stores h straight to peer p (1 st + 1 release-arrive).
// Local STS + bar + own-slice partial for t+1 hide under the DSMEM flight.
// Full fp32, __expf-based activations.

#define L_SEQ   262144
#define H_DIM   128
#define SLICE   32
#define CN      4
#define NT      128
#define CHUNK   1024
#define RPT     24      // remote cols per thread (96/4)
#define OPT     8       // own cols per thread (32/4)
#define N_ARRV  96      // remote arrivals per phase (3 peers x 32 lanes)

__device__ __forceinline__ float sigmoid_f(float x) {
    return __fdividef(1.0f, 1.0f + __expf(-x));
}
__device__ __forceinline__ float tanh_f(float x) {
    return 1.0f - __fdividef(2.0f, 1.0f + __expf(2.0f * x));
}

__device__ __forceinline__ uint32_t smem_u32(const void* ptr) {
    uint32_t a;
    asm("{ .reg .u64 t; cvta.to.shared.u64 t, %1; cvt.u32.u64 %0, t; }"
        : "=r"(a) : "l"(ptr));
    return a;
}
__device__ __forceinline__ uint32_t cluster_rank_() {
    uint32_t v; asm("mov.u32 %0, %%cluster_ctarank;" : "=r"(v)); return v;
}
__device__ __forceinline__ uint32_t mapa_u32(uint32_t addr, uint32_t rk) {
    uint32_t v;
    asm("mapa.shared::cluster.u32 %0, %1, %2;" : "=r"(v) : "r"(addr), "r"(rk));
    return v;
}
__device__ __forceinline__ void sts_cluster_f32(uint32_t raddr, float v) {
    asm volatile("st.shared::cluster.f32 [%0], %1;"
                 :: "r"(raddr), "f"(v) : "memory");
}
__device__ __forceinline__ void mbar_arrive_rel_cluster(uint32_t raddr) {
    asm volatile("mbarrier.arrive.release.cluster.shared::cluster.b64 _, [%0];"
                 :: "r"(raddr) : "memory");
}
__device__ __forceinline__ void mbar_init(uint32_t addr, uint32_t count) {
    asm volatile("mbarrier.init.shared.b64 [%0], %1;"
                 :: "r"(addr), "r"(count) : "memory");
}
__device__ __forceinline__ void mbar_wait_parity_acq_cluster(uint32_t addr,
                                                             uint32_t parity) {
    uint32_t done;
    asm volatile(
        "{\n\t.reg .pred p;\n\t"
        "mbarrier.try_wait.parity.acquire.cluster.shared::cta.b64 p, [%1], %2;\n\t"
        "selp.b32 %0, 1, 0, p;\n\t}"
        : "=r"(done) : "r"(addr), "r"(parity) : "memory");
    if (!done) {
        asm volatile(
            "{\n\t.reg .pred P1;\n\t"
            "WL_%=:\n\t"
            "mbarrier.try_wait.parity.acquire.cluster.shared::cta.b64 P1, [%0], %1, 0x989680;\n\t"
            "@P1 bra.uni WD_%=;\n\t"
            "bra.uni WL_%=;\n\t"
            "WD_%=:\n\t}"
            :: "r"(addr), "r"(parity) : "memory");
    }
}
#define CLUSTER_SYNC_() do { \
    asm volatile("barrier.cluster.arrive.aligned;" ::: "memory"); \
    asm volatile("barrier.cluster.wait.aligned;" ::: "memory"); \
} while (0)

__global__ void __launch_bounds__(NT, 1) __cluster_dims__(CN, 1, 1)
lstm_quad_kernel(const float* __restrict__ sentence,
                 const float* __restrict__ W_ih,
                 const float* __restrict__ W_hh,
                 const float* __restrict__ b_ih,
                 const float* __restrict__ b_hh,
                 const float* __restrict__ W_out,
                 const float* __restrict__ b_out,
                 float* __restrict__ out)
{
    __shared__ alignas(8)  unsigned long long mbar;
    __shared__ alignas(16) float hbuf[2][H_DIM];
    __shared__ alignas(16) float xbuf[CHUNK * 2];

    const int r = threadIdx.x;
    const int q = r >> 2;                 // quad id 0..31 -> h-index
    const int p = r & 3;                  // k-part / target peer
    const uint32_t rank = cluster_rank_();
    const int hidx = (int)rank * SLICE + q;

    // remote col window start (contiguous 96 cols beginning at next CTA slice)
    const int K0 = ((int)rank + 1) * SLICE + p * RPT;   // use (K0+jj)&127
    const int OWN0 = (int)rank * SLICE + p * OPT;       // own col start

    // Register weights: 4 gates x (24 remote + 8 own).
    // Affine terms pre-scaled by 0.25: the quad-reduce sums the identical
    // affine contribution from all 4 lanes (0.25 scaling is exact in fp32).
    float Wr[4][RPT], Wo[4][OPT];
    float xw0[4], xw1[4], xb[4];
#pragma unroll
    for (int g = 0; g < 4; ++g) {
        const int gr = g * H_DIM + hidx;
        const float* wrow = W_hh + gr * H_DIM;
#pragma unroll
        for (int jj = 0; jj < RPT; ++jj) Wr[g][jj] = wrow[(K0 + jj) & (H_DIM - 1)];
#pragma unroll
        for (int j = 0; j < OPT; ++j)    Wo[g][j]  = wrow[OWN0 + j];
        xw0[g] = 0.25f * W_ih[2 * gr + 0];
        xw1[g] = 0.25f * W_ih[2 * gr + 1];
        xb[g]  = 0.25f * (b_ih[gr] + b_hh[gr]);
    }

    // init
    if (r < H_DIM) { hbuf[0][r] = 0.0f; hbuf[1][r] = 0.0f; }
    const uint32_t bar_addr = smem_u32(&mbar);
    const uint32_t hb_addr  = smem_u32(&hbuf[0][0]);
    if (r == 0) mbar_init(bar_addr, N_ARRV);
    __syncthreads();
    CLUSTER_SYNC_();

    // per-thread peer addresses (lane p targets CTA p)
    const uint32_t peer_h   = mapa_u32(hb_addr,  (uint32_t)p);
    const uint32_t peer_bar = mapa_u32(bar_addr, (uint32_t)p);
    const uint32_t my_off   = (uint32_t)hidx * 4u;   // byte offset of my h
    const bool is_remote    = ((uint32_t)p != rank);

    float c_reg = 0.0f;
    float part0 = 0.0f, part1 = 0.0f, part2 = 0.0f, part3 = 0.0f;

    for (int t0 = 0; t0 < L_SEQ; t0 += CHUNK) {
        // refill x chunk (2048 floats = 512 float4)
        {
            const float4* src = (const float4*)(sentence + 2 * t0);
            float4* dst = (float4*)xbuf;
#pragma unroll
            for (int j = 0; j < 4; ++j) dst[r + j * NT] = src[r + j * NT];
        }
        __syncthreads();

#pragma unroll 1
        for (int ti = 0; ti < CHUNK; ++ti) {
            const int t = t0 + ti;
            // wait for remote slices of h(t) (phase t-1); t=0 uses zeros
            if (t != 0) mbar_wait_parity_acq_cluster(bar_addr, (uint32_t)((t - 1) & 1));

            // ---- phase A: remote 24 cols x 4 gates (+scaled x-term, +own partial)
            const float x0 = xbuf[2 * ti + 0];
            const float x1 = xbuf[2 * ti + 1];
            float a0[4], a1[4];
            a0[0] = fmaf(xw0[0], x0, xb[0] + part0); a1[0] = xw1[0] * x1;
            a0[1] = fmaf(xw0[1], x0, xb[1] + part1); a1[1] = xw1[1] * x1;
            a0[2] = fmaf(xw0[2], x0, xb[2] + part2); a1[2] = xw1[2] * x1;
            a0[3] = fmaf(xw0[3], x0, xb[3] + part3); a1[3] = xw1[3] * x1;

            const float* hr = &hbuf[t & 1][0];
#pragma unroll
            for (int jj = 0; jj < RPT; jj += 2) {
                const float h0 = hr[(K0 + jj)     & (H_DIM - 1)];
                const float h1 = hr[(K0 + jj + 1) & (H_DIM - 1)];
#pragma unroll
                for (int g = 0; g < 4; ++g) {
                    a0[g] = fmaf(Wr[g][jj],     h0, a0[g]);
                    a1[g] = fmaf(Wr[g][jj + 1], h1, a1[g]);
                }
            }
            float s0 = a0[0] + a1[0];
            float s1 = a0[1] + a1[1];
            float s2 = a0[2] + a1[2];
            float s3 = a0[3] + a1[3];

            // ---- quad reduce: every lane ends with all 4 gate sums
            s0 += __shfl_xor_sync(0xffffffffu, s0, 1);
            s1 += __shfl_xor_sync(0xffffffffu, s1, 1);
            s2 += __shfl_xor_sync(0xffffffffu, s2, 1);
            s3 += __shfl_xor_sync(0xffffffffu, s3, 1);
            s0 += __shfl_xor_sync(0xffffffffu, s0, 2);
            s1 += __shfl_xor_sync(0xffffffffu, s1, 2);
            s2 += __shfl_xor_sync(0xffffffffu, s2, 2);
            s3 += __shfl_xor_sync(0xffffffffu, s3, 2);

            // ---- activations + c/h (redundant across quad lanes)
            const float iv = sigmoid_f(s0);
            const float fv = sigmoid_f(s1);
            const float gv = tanh_f(s2);
            const float ov = sigmoid_f(s3);
            c_reg = fmaf(fv, c_reg, iv * gv);
            const float h = ov * tanh_f(c_reg);

            // ---- store h IMMEDIATELY: lane p -> CTA p
            const int wb = (t + 1) & 1;
            if (is_remote) {
                sts_cluster_f32(peer_h + (uint32_t)(wb * H_DIM * 4) + my_off, h);
                mbar_arrive_rel_cluster(peer_bar);
            } else {
                hbuf[wb][hidx] = h;          // local slice
            }

            // ---- overlap window (DSMEM in flight): local sync + own partial
            __syncthreads();
            {
                const float2* ho = (const float2*)(&hbuf[wb][OWN0]);
                float b0[4] = {0, 0, 0, 0}, b1[4] = {0, 0, 0, 0};
#pragma unroll
                for (int j = 0; j < OPT / 2; ++j) {
                    const float2 hv = ho[j];
#pragma unroll
                    for (int g = 0; g < 4; ++g) {
                        b0[g] = fmaf(Wo[g][2 * j],     hv.x, b0[g]);
                        b1[g] = fmaf(Wo[g][2 * j + 1], hv.y, b1[g]);
                    }
                }
                part0 = b0[0] + b1[0];
                part1 = b0[1] + b1[1];
                part2 = b0[2] + b1[2];
                part3 = b0[3] + b1[3];
            }
        }
    }

    // final wait: remote slices of h(L) (phase L-1, parity 1)
    mbar_wait_parity_acq_cluster(bar_addr, (uint32_t)((L_SEQ - 1) & 1));

    // Outputs: out[0]=sigmoid(h.W_out+b), out[1..128]=h_n, out[129..256]=c_n
    if (p == 0) out[1 + H_DIM + hidx] = c_reg;      // this CTA's 32 c values
    if (rank == 0) {
        const float* hf = &hbuf[L_SEQ & 1][0];      // = hbuf[0]
        if (r < H_DIM) out[1 + r] = hf[r];
        if (r < 32) {
            float s = 0.0f;
#pragma unroll
            for (int m = 0; m < 4; ++m)
                s = fmaf(hf[4 * r + m], W_out[4 * r + m], s);
#pragma unroll
            for (int off = 16; off > 0; off >>= 1)
                s += __shfl_xor_sync(0xffffffffu, s, off);
            if (r == 0) out[0] = sigmoid_f(s + b_out[0]);
        }
    }
    CLUSTER_SYNC_();
}

extern "C" void kernel_launch(void* const* d_in, const int* in_sizes, int n_in,
                              void* d_out, int out_size)
{
    const float* sentence = (const float*)d_in[0];
    const float* W_ih     = (const float*)d_in[1];
    const float* W_hh     = (const float*)d_in[2];
    const float* b_ih     = (const float*)d_in[3];
    const float* b_hh     = (const float*)d_in[4];
    const float* W_out    = (const float*)d_in[5];
    const float* b_out    = (const float*)d_in[6];
    float* out            = (float*)d_out;

    lstm_quad_kernel<<<CN, NT>>>(
        sentence, W_ih, W_hh, b_ih, b_hh, W_out, b_out, out);
}

// round 11
// speedup vs baseline: 1.0192x; 1.0192x over previous
#include <cuda_runtime.h>
#include <cstdint>

// LSTMTagger: 262144 sequential steps, H=128 (512 gate rows), I=2.
// R10 = R9 resubmitted (previous round died to an infra flake before running;
// sync design re-audited, no defect found).
// 4-CTA cluster, 128 thr/CTA (thread = one gate row):
//  - all 128 W_hh cols in regs, permuted so own-CTA slice is first
//  - all 4 warps compute c/h redundantly; warp w stores h ONLY to peer w
//    (1 st.shared::cluster + 1 release-arrive right after h) -> store fanout
//    parallel across SMSPs, no single-producer serialization
//  - own-slice partial gemv for t+1 runs inside the DSMEM flight window
//  - x-term computed before the mbarrier wait
// Full fp32, __expf activations (proven ~7e-7 path). Double-buffered h.

#define L_SEQ   262144
#define H_DIM   128
#define SLICE   32
#define CN      4
#define NT      128
#define CHUNK   1024
#define N_ARRV  96      // 3 remote warps x 32 lanes per phase

__device__ __forceinline__ float sigmoid_f(float x) {
    return __fdividef(1.0f, 1.0f + __expf(-x));
}
__device__ __forceinline__ float tanh_f(float x) {
    return 1.0f - __fdividef(2.0f, 1.0f + __expf(2.0f * x));
}

__device__ __forceinline__ uint32_t smem_u32(const void* ptr) {
    uint32_t a;
    asm("{ .reg .u64 t; cvta.to.shared.u64 t, %1; cvt.u32.u64 %0, t; }"
        : "=r"(a) : "l"(ptr));
    return a;
}
__device__ __forceinline__ uint32_t cluster_rank_() {
    uint32_t v; asm("mov.u32 %0, %%cluster_ctarank;" : "=r"(v)); return v;
}
__device__ __forceinline__ uint32_t mapa_u32(uint32_t addr, uint32_t rk) {
    uint32_t v;
    asm("mapa.shared::cluster.u32 %0, %1, %2;" : "=r"(v) : "r"(addr), "r"(rk));
    return v;
}
__device__ __forceinline__ void sts_cluster_f32(uint32_t raddr, float v) {
    asm volatile("st.shared::cluster.f32 [%0], %1;"
                 :: "r"(raddr), "f"(v) : "memory");
}
__device__ __forceinline__ void mbar_arrive_rel_cluster(uint32_t raddr) {
    asm volatile("mbarrier.arrive.release.cluster.shared::cluster.b64 _, [%0];"
                 :: "r"(raddr) : "memory");
}
__device__ __forceinline__ void mbar_init(uint32_t addr, uint32_t count) {
    asm volatile("mbarrier.init.shared.b64 [%0], %1;"
                 :: "r"(addr), "r"(count) : "memory");
}
__device__ __forceinline__ void mbar_wait_parity_acq_cluster(uint32_t addr,
                                                             uint32_t parity) {
    uint32_t done;
    asm volatile(
        "{\n\t.reg .pred p;\n\t"
        "mbarrier.try_wait.parity.acquire.cluster.shared::cta.b64 p, [%1], %2;\n\t"
        "selp.b32 %0, 1, 0, p;\n\t}"
        : "=r"(done) : "r"(addr), "r"(parity) : "memory");
    if (!done) {
        asm volatile(
            "{\n\t.reg .pred P1;\n\t"
            "WL_%=:\n\t"
            "mbarrier.try_wait.parity.acquire.cluster.shared::cta.b64 P1, [%0], %1, 0x989680;\n\t"
            "@P1 bra.uni WD_%=;\n\t"
            "bra.uni WL_%=;\n\t"
            "WD_%=:\n\t}"
            :: "r"(addr), "r"(parity) : "memory");
    }
}
#define CLUSTER_SYNC_() do { \
    asm volatile("barrier.cluster.arrive.aligned;" ::: "memory"); \
    asm volatile("barrier.cluster.wait.aligned;" ::: "memory"); \
} while (0)

__global__ void __launch_bounds__(NT, 1) __cluster_dims__(CN, 1, 1)
lstm_r10_kernel(const float* __restrict__ sentence,
                const float* __restrict__ W_ih,
                const float* __restrict__ W_hh,
                const float* __restrict__ b_ih,
                const float* __restrict__ b_hh,
                const float* __restrict__ W_out,
                const float* __restrict__ b_out,
                float* __restrict__ out)
{
    __shared__ alignas(8)  unsigned long long mbar;
    __shared__ alignas(16) float hbuf[2][H_DIM];
    __shared__ alignas(16) float gact[NT];
    __shared__ alignas(16) float xbuf[CHUNK * 2];

    const int r    = threadIdx.x;     // 0..127
    const int lane = r & 31;
    const int w    = r >> 5;          // warp id = gate id = target peer
    const uint32_t rank = cluster_rank_();
    const int hidx = (int)rank * SLICE + lane;

    const int gr = w * H_DIM + hidx;  // this thread's gate row

    const float wih0 = W_ih[2 * gr + 0];
    const float wih1 = W_ih[2 * gr + 1];
    const float br   = b_ih[gr] + b_hh[gr];

    // W_hh row in regs, permuted: W[m] <-> h column ((32*rank + m) & 127).
    // W[0..31] = own slice, W[32..127] = remote slices in ring order.
    float W[H_DIM];
#pragma unroll
    for (int m = 0; m < H_DIM; ++m)
        W[m] = W_hh[gr * H_DIM + (((int)rank * SLICE + m) & (H_DIM - 1))];

    // init
    if (r < H_DIM) { hbuf[0][r] = 0.0f; hbuf[1][r] = 0.0f; }
    const uint32_t bar_addr = smem_u32(&mbar);
    const uint32_t hb_addr  = smem_u32(&hbuf[0][0]);
    if (r == 0) mbar_init(bar_addr, N_ARRV);
    __syncthreads();
    CLUSTER_SYNC_();

    // warp w targets peer CTA w
    const uint32_t peer_h   = mapa_u32(hb_addr,  (uint32_t)w);
    const uint32_t peer_bar = mapa_u32(bar_addr, (uint32_t)w);
    const uint32_t my_off   = (uint32_t)hidx * 4u;
    const bool is_remote    = ((uint32_t)w != rank);

    float c_reg = 0.0f;                         // redundant across warps
    float part  = 0.0f;                         // own-slice partial (h(0)=0)

    for (int t0 = 0; t0 < L_SEQ; t0 += CHUNK) {
        {   // refill x chunk (2048 floats = 512 float4)
            const float4* src = (const float4*)(sentence + 2 * t0);
            float4* dst = (float4*)xbuf;
#pragma unroll
            for (int j = 0; j < 4; ++j) dst[r + j * NT] = src[r + j * NT];
        }
        __syncthreads();

#pragma unroll 1
        for (int ti = 0; ti < CHUNK; ++ti) {
            const int t = t0 + ti;

            // x-term + own partial: no hbuf dependence -> before the wait
            const float x0 = xbuf[2 * ti + 0];
            const float x1 = xbuf[2 * ti + 1];
            float acc0 = fmaf(wih0, x0, br) + part;
            float acc1 = wih1 * x1;
            float acc2 = 0.0f, acc3 = 0.0f;

            // wait for remote slices of h(t); t=0 uses zeros
            if (t != 0) mbar_wait_parity_acq_cluster(bar_addr, (uint32_t)((t - 1) & 1));

            // remote 96 cols, broadcast float4 LDS (W[32..127])
            {
                const float* hr = &hbuf[t & 1][0];
#pragma unroll
                for (int i = 1; i < CN; ++i) {
                    const uint32_t s = (rank + (uint32_t)i) & (CN - 1);
                    const float4* h4 = (const float4*)(hr + s * SLICE);
#pragma unroll
                    for (int q = 0; q < SLICE / 4; ++q) {
                        const float4 hv = h4[q];
                        acc0 = fmaf(W[SLICE * i + 4 * q + 0], hv.x, acc0);
                        acc1 = fmaf(W[SLICE * i + 4 * q + 1], hv.y, acc1);
                        acc2 = fmaf(W[SLICE * i + 4 * q + 2], hv.z, acc2);
                        acc3 = fmaf(W[SLICE * i + 4 * q + 3], hv.w, acc3);
                    }
                }
            }
            const float g = (acc0 + acc2) + (acc1 + acc3);

            // publish own gate activation
            gact[r] = (w == 2) ? tanh_f(g) : sigmoid_f(g);
            __syncthreads();                               // S1

            // ALL warps: redundant c/h for h-index hidx
            const float iv = gact[lane];
            const float fv = gact[32 + lane];
            const float gv = gact[64 + lane];
            const float ov = gact[96 + lane];
            c_reg = fmaf(fv, c_reg, iv * gv);
            const float h = ov * tanh_f(c_reg);

            // store IMMEDIATELY: warp w -> peer w (after S1, so all gemv
            // reads of this CTA precede the arrive -> double-buffer safe)
            const int wb = (t + 1) & 1;
            if (is_remote) {
                sts_cluster_f32(peer_h + (uint32_t)(wb * H_DIM * 4) + my_off, h);
                mbar_arrive_rel_cluster(peer_bar);
            } else {
                hbuf[wb][hidx] = h;                        // local slice
            }

            // overlap window (DSMEM in flight): publish local slice, then
            // own-slice partial of g(t+1)  (W[0..31])
            __syncthreads();                               // S2
            {
                const float4* h4 = (const float4*)(&hbuf[wb][0] + rank * SLICE);
                float p0 = 0.0f, p1 = 0.0f, p2 = 0.0f, p3 = 0.0f;
#pragma unroll
                for (int q = 0; q < SLICE / 4; ++q) {
                    const float4 hv = h4[q];
                    p0 = fmaf(W[4 * q + 0], hv.x, p0);
                    p1 = fmaf(W[4 * q + 1], hv.y, p1);
                    p2 = fmaf(W[4 * q + 2], hv.z, p2);
                    p3 = fmaf(W[4 * q + 3], hv.w, p3);
                }
                part = (p0 + p2) + (p1 + p3);
            }
        }
    }

    // final wait: remote slices of h(L) (phase (L-1)&1 = 1)
    mbar_wait_parity_acq_cluster(bar_addr, (uint32_t)((L_SEQ - 1) & 1));

    // Outputs: out[0]=sigmoid(h.W_out+b), out[1..128]=h_n, out[129..256]=c_n
    if (w == 0) out[1 + H_DIM + hidx] = c_reg;   // 32 c values per CTA
    if (rank == 0) {
        const float* hf = &hbuf[L_SEQ & 1][0];   // = hbuf[0]
        if (r < H_DIM) out[1 + r] = hf[r];
        if (r < 32) {
            float s = 0.0f;
#pragma unroll
            for (int m = 0; m < 4; ++m)
                s = fmaf(hf[4 * r + m], W_out[4 * r + m], s);
#pragma unroll
            for (int off = 16; off > 0; off >>= 1)
                s += __shfl_xor_sync(0xffffffffu, s, off);
            if (r == 0) out[0] = sigmoid_f(s + b_out[0]);
        }
    }
    CLUSTER_SYNC_();
}

extern "C" void kernel_launch(void* const* d_in, const int* in_sizes, int n_in,
                              void* d_out, int out_size)
{
    const float* sentence = (const float*)d_in[0];
    const float* W_ih     = (const float*)d_in[1];
    const float* W_hh     = (const float*)d_in[2];
    const float* b_ih     = (const float*)d_in[3];
    const float* b_hh     = (const float*)d_in[4];
    const float* W_out    = (const float*)d_in[5];
    const float* b_out    = (const float*)d_in[6];
    float* out            = (float*)d_out;

    lstm_r10_kernel<<<CN, NT>>>(
        sentence, W_ih, W_hh, b_ih, b_hh, W_out, b_out, out);
}

// round 12
// speedup vs baseline: 1.5301x; 1.5012x over previous
#include <cuda_runtime.h>
#include <cstdint>

// LSTMTagger: 262144 sequential steps, H=128 (512 gate rows), I=2.
// R11 = R10 with ONE change: plain mbarrier.arrive.shared::cluster (the
// explicit .release.cluster arrive correlates with a ~40ms regression across
// R8/R9/R10 vs the plain-arrive R5/R6; single-variable test).
// 4-CTA cluster, 128 thr/CTA (thread = one gate row):
//  - all 128 W_hh cols in regs, permuted so own-CTA slice is first
//  - all 4 warps compute c/h redundantly; warp w stores h ONLY to peer w
//  - own-slice partial gemv for t+1 runs inside the DSMEM flight window
//  - x-term computed before the mbarrier wait
// Full fp32, __expf activations. Double-buffered h.

#define L_SEQ   262144
#define H_DIM   128
#define SLICE   32
#define CN      4
#define NT      128
#define CHUNK   1024
#define N_ARRV  96      // 3 remote warps x 32 lanes per phase

__device__ __forceinline__ float sigmoid_f(float x) {
    return __fdividef(1.0f, 1.0f + __expf(-x));
}
__device__ __forceinline__ float tanh_f(float x) {
    return 1.0f - __fdividef(2.0f, 1.0f + __expf(2.0f * x));
}

__device__ __forceinline__ uint32_t smem_u32(const void* ptr) {
    uint32_t a;
    asm("{ .reg .u64 t; cvta.to.shared.u64 t, %1; cvt.u32.u64 %0, t; }"
        : "=r"(a) : "l"(ptr));
    return a;
}
__device__ __forceinline__ uint32_t cluster_rank_() {
    uint32_t v; asm("mov.u32 %0, %%cluster_ctarank;" : "=r"(v)); return v;
}
__device__ __forceinline__ uint32_t mapa_u32(uint32_t addr, uint32_t rk) {
    uint32_t v;
    asm("mapa.shared::cluster.u32 %0, %1, %2;" : "=r"(v) : "r"(addr), "r"(rk));
    return v;
}
__device__ __forceinline__ void sts_cluster_f32(uint32_t raddr, float v) {
    asm volatile("st.shared::cluster.f32 [%0], %1;"
                 :: "r"(raddr), "f"(v) : "memory");
}
// PLAIN arrive on a (possibly remote) cluster smem barrier — the R5/R6 path.
__device__ __forceinline__ void mbar_arrive_cluster(uint32_t raddr) {
    asm volatile("mbarrier.arrive.shared::cluster.b64 _, [%0];"
                 :: "r"(raddr) : "memory");
}
__device__ __forceinline__ void mbar_init(uint32_t addr, uint32_t count) {
    asm volatile("mbarrier.init.shared.b64 [%0], %1;"
                 :: "r"(addr), "r"(count) : "memory");
}
__device__ __forceinline__ void mbar_wait_parity_acq_cluster(uint32_t addr,
                                                             uint32_t parity) {
    uint32_t done;
    asm volatile(
        "{\n\t.reg .pred p;\n\t"
        "mbarrier.try_wait.parity.acquire.cluster.shared::cta.b64 p, [%1], %2;\n\t"
        "selp.b32 %0, 1, 0, p;\n\t}"
        : "=r"(done) : "r"(addr), "r"(parity) : "memory");
    if (!done) {
        asm volatile(
            "{\n\t.reg .pred P1;\n\t"
            "WL_%=:\n\t"
            "mbarrier.try_wait.parity.acquire.cluster.shared::cta.b64 P1, [%0], %1, 0x989680;\n\t"
            "@P1 bra.uni WD_%=;\n\t"
            "bra.uni WL_%=;\n\t"
            "WD_%=:\n\t}"
            :: "r"(addr), "r"(parity) : "memory");
    }
}
#define CLUSTER_SYNC_() do { \
    asm volatile("barrier.cluster.arrive.aligned;" ::: "memory"); \
    asm volatile("barrier.cluster.wait.aligned;" ::: "memory"); \
} while (0)

__global__ void __launch_bounds__(NT, 1) __cluster_dims__(CN, 1, 1)
lstm_r11_kernel(const float* __restrict__ sentence,
                const float* __restrict__ W_ih,
                const float* __restrict__ W_hh,
                const float* __restrict__ b_ih,
                const float* __restrict__ b_hh,
                const float* __restrict__ W_out,
                const float* __restrict__ b_out,
                float* __restrict__ out)
{
    __shared__ alignas(8)  unsigned long long mbar;
    __shared__ alignas(16) float hbuf[2][H_DIM];
    __shared__ alignas(16) float gact[NT];
    __shared__ alignas(16) float xbuf[CHUNK * 2];

    const int r    = threadIdx.x;     // 0..127
    const int lane = r & 31;
    const int w    = r >> 5;          // warp id = gate id = target peer
    const uint32_t rank = cluster_rank_();
    const int hidx = (int)rank * SLICE + lane;

    const int gr = w * H_DIM + hidx;  // this thread's gate row

    const float wih0 = W_ih[2 * gr + 0];
    const float wih1 = W_ih[2 * gr + 1];
    const float br   = b_ih[gr] + b_hh[gr];

    // W_hh row in regs, permuted: W[m] <-> h column ((32*rank + m) & 127).
    float W[H_DIM];
#pragma unroll
    for (int m = 0; m < H_DIM; ++m)
        W[m] = W_hh[gr * H_DIM + (((int)rank * SLICE + m) & (H_DIM - 1))];

    // init
    if (r < H_DIM) { hbuf[0][r] = 0.0f; hbuf[1][r] = 0.0f; }
    const uint32_t bar_addr = smem_u32(&mbar);
    const uint32_t hb_addr  = smem_u32(&hbuf[0][0]);
    if (r == 0) mbar_init(bar_addr, N_ARRV);
    __syncthreads();
    CLUSTER_SYNC_();

    // warp w targets peer CTA w
    const uint32_t peer_h   = mapa_u32(hb_addr,  (uint32_t)w);
    const uint32_t peer_bar = mapa_u32(bar_addr, (uint32_t)w);
    const uint32_t my_off   = (uint32_t)hidx * 4u;
    const bool is_remote    = ((uint32_t)w != rank);

    float c_reg = 0.0f;                         // redundant across warps
    float part  = 0.0f;                         // own-slice partial (h(0)=0)

    for (int t0 = 0; t0 < L_SEQ; t0 += CHUNK) {
        {   // refill x chunk (2048 floats = 512 float4)
            const float4* src = (const float4*)(sentence + 2 * t0);
            float4* dst = (float4*)xbuf;
#pragma unroll
            for (int j = 0; j < 4; ++j) dst[r + j * NT] = src[r + j * NT];
        }
        __syncthreads();

#pragma unroll 1
        for (int ti = 0; ti < CHUNK; ++ti) {
            const int t = t0 + ti;

            // x-term + own partial: no hbuf dependence -> before the wait
            const float x0 = xbuf[2 * ti + 0];
            const float x1 = xbuf[2 * ti + 1];
            float acc0 = fmaf(wih0, x0, br) + part;
            float acc1 = wih1 * x1;
            float acc2 = 0.0f, acc3 = 0.0f;

            // wait for remote slices of h(t); t=0 uses zeros
            if (t != 0) mbar_wait_parity_acq_cluster(bar_addr, (uint32_t)((t - 1) & 1));

            // remote 96 cols, broadcast float4 LDS (W[32..127])
            {
                const float* hr = &hbuf[t & 1][0];
#pragma unroll
                for (int i = 1; i < CN; ++i) {
                    const uint32_t s = (rank + (uint32_t)i) & (CN - 1);
                    const float4* h4 = (const float4*)(hr + s * SLICE);
#pragma unroll
                    for (int q = 0; q < SLICE / 4; ++q) {
                        const float4 hv = h4[q];
                        acc0 = fmaf(W[SLICE * i + 4 * q + 0], hv.x, acc0);
                        acc1 = fmaf(W[SLICE * i + 4 * q + 1], hv.y, acc1);
                        acc2 = fmaf(W[SLICE * i + 4 * q + 2], hv.z, acc2);
                        acc3 = fmaf(W[SLICE * i + 4 * q + 3], hv.w, acc3);
                    }
                }
            }
            const float g = (acc0 + acc2) + (acc1 + acc3);

            // publish own gate activation
            gact[r] = (w == 2) ? tanh_f(g) : sigmoid_f(g);
            __syncthreads();                               // S1

            // ALL warps: redundant c/h for h-index hidx
            const float iv = gact[lane];
            const float fv = gact[32 + lane];
            const float gv = gact[64 + lane];
            const float ov = gact[96 + lane];
            c_reg = fmaf(fv, c_reg, iv * gv);
            const float h = ov * tanh_f(c_reg);

            // store IMMEDIATELY: warp w -> peer w (after S1, so all gemv
            // reads of this CTA precede the arrive -> double-buffer safe)
            const int wb = (t + 1) & 1;
            if (is_remote) {
                sts_cluster_f32(peer_h + (uint32_t)(wb * H_DIM * 4) + my_off, h);
                mbar_arrive_cluster(peer_bar);             // PLAIN arrive
            } else {
                hbuf[wb][hidx] = h;                        // local slice
            }

            // overlap window (DSMEM in flight): publish local slice, then
            // own-slice partial of g(t+1)  (W[0..31])
            __syncthreads();                               // S2
            {
                const float4* h4 = (const float4*)(&hbuf[wb][0] + rank * SLICE);
                float p0 = 0.0f, p1 = 0.0f, p2 = 0.0f, p3 = 0.0f;
#pragma unroll
                for (int q = 0; q < SLICE / 4; ++q) {
                    const float4 hv = h4[q];
                    p0 = fmaf(W[4 * q + 0], hv.x, p0);
                    p1 = fmaf(W[4 * q + 1], hv.y, p1);
                    p2 = fmaf(W[4 * q + 2], hv.z, p2);
                    p3 = fmaf(W[4 * q + 3], hv.w, p3);
                }
                part = (p0 + p2) + (p1 + p3);
            }
        }
    }

    // final wait: remote slices of h(L) (phase (L-1)&1 = 1)
    mbar_wait_parity_acq_cluster(bar_addr, (uint32_t)((L_SEQ - 1) & 1));

    // Outputs: out[0]=sigmoid(h.W_out+b), out[1..128]=h_n, out[129..256]=c_n
    if (w == 0) out[1 + H_DIM + hidx] = c_reg;   // 32 c values per CTA
    if (rank == 0) {
        const float* hf = &hbuf[L_SEQ & 1][0];   // = hbuf[0]
        if (r < H_DIM) out[1 + r] = hf[r];
        if (r < 32) {
            float s = 0.0f;
#pragma unroll
            for (int m = 0; m < 4; ++m)
                s = fmaf(hf[4 * r + m], W_out[4 * r + m], s);
#pragma unroll
            for (int off = 16; off > 0; off >>= 1)
                s += __shfl_xor_sync(0xffffffffu, s, off);
            if (r == 0) out[0] = sigmoid_f(s + b_out[0]);
        }
    }
    CLUSTER_SYNC_();
}

extern "C" void kernel_launch(void* const* d_in, const int* in_sizes, int n_in,
                              void* d_out, int out_size)
{
    const float* sentence = (const float*)d_in[0];
    const float* W_ih     = (const float*)d_in[1];
    const float* W_hh     = (const float*)d_in[2];
    const float* b_ih     = (const float*)d_in[3];
    const float* b_hh     = (const float*)d_in[4];
    const float* W_out    = (const float*)d_in[5];
    const float* b_out    = (const float*)d_in[6];
    float* out            = (float*)d_out;

    lstm_r11_kernel<<<CN, NT>>>(
        sentence, W_ih, W_hh, b_ih, b_hh, W_out, b_out, out);
}

// round 13
// speedup vs baseline: 1.6147x; 1.0553x over previous
#include <cuda_runtime.h>
#include <cstdint>

// LSTMTagger: 262144 sequential steps, H=128 (512 gate rows), I=2.
// R12: 4-CTA cluster, 128 thr/CTA, in-warp gate transpose:
//   warp w, lane l -> gate (l>>3), h-index rank*32 + 8w + (l&7).
//   All 4 gates of an h-index live in ONE warp -> gate combine is 4 shfl.idx
//   (no gact smem, no S1 barrier). Gate-2 (tanh) handled branchlessly via
//   2*sigma(2g)-1 with exactly-scaled (x2) weights.
//   All lanes compute c/h redundantly; lane-group g stores h to peer
//   (rank+g)&3 -> store fanout fully parallel, plain cluster arrives
//   (explicit .release arrives cost ~190cyc/step -- R11 finding).
//   Own-slice partial gemv for t+1 + S2 hide under the DSMEM flight.
// Full fp32, __expf activations. Double-buffered h.

#define L_SEQ   262144
#define H_DIM   128
#define SLICE   32
#define CN      4
#define NT      128
#define CHUNK   1024
#define N_ARRV  96      // 3 peers x (4 warps x 8 lanes) per phase

__device__ __forceinline__ float sigmoid_f(float x) {
    return __fdividef(1.0f, 1.0f + __expf(-x));
}
__device__ __forceinline__ float tanh_f(float x) {
    return 1.0f - __fdividef(2.0f, 1.0f + __expf(2.0f * x));
}

__device__ __forceinline__ uint32_t smem_u32(const void* ptr) {
    uint32_t a;
    asm("{ .reg .u64 t; cvta.to.shared.u64 t, %1; cvt.u32.u64 %0, t; }"
        : "=r"(a) : "l"(ptr));
    return a;
}
__device__ __forceinline__ uint32_t cluster_rank_() {
    uint32_t v; asm("mov.u32 %0, %%cluster_ctarank;" : "=r"(v)); return v;
}
__device__ __forceinline__ uint32_t mapa_u32(uint32_t addr, uint32_t rk) {
    uint32_t v;
    asm("mapa.shared::cluster.u32 %0, %1, %2;" : "=r"(v) : "r"(addr), "r"(rk));
    return v;
}
__device__ __forceinline__ void sts_cluster_f32(uint32_t raddr, float v) {
    asm volatile("st.shared::cluster.f32 [%0], %1;"
                 :: "r"(raddr), "f"(v) : "memory");
}
// PLAIN arrive (R11 finding: explicit .release.cluster costs ~40ms here)
__device__ __forceinline__ void mbar_arrive_cluster(uint32_t raddr) {
    asm volatile("mbarrier.arrive.shared::cluster.b64 _, [%0];"
                 :: "r"(raddr) : "memory");
}
__device__ __forceinline__ void mbar_init(uint32_t addr, uint32_t count) {
    asm volatile("mbarrier.init.shared.b64 [%0], %1;"
                 :: "r"(addr), "r"(count) : "memory");
}
__device__ __forceinline__ void mbar_wait_parity_acq_cluster(uint32_t addr,
                                                             uint32_t parity) {
    uint32_t done;
    asm volatile(
        "{\n\t.reg .pred p;\n\t"
        "mbarrier.try_wait.parity.acquire.cluster.shared::cta.b64 p, [%1], %2;\n\t"
        "selp.b32 %0, 1, 0, p;\n\t}"
        : "=r"(done) : "r"(addr), "r"(parity) : "memory");
    if (!done) {
        asm volatile(
            "{\n\t.reg .pred P1;\n\t"
            "WL_%=:\n\t"
            "mbarrier.try_wait.parity.acquire.cluster.shared::cta.b64 P1, [%0], %1, 0x989680;\n\t"
            "@P1 bra.uni WD_%=;\n\t"
            "bra.uni WL_%=;\n\t"
            "WD_%=:\n\t}"
            :: "r"(addr), "r"(parity) : "memory");
    }
}
#define CLUSTER_SYNC_() do { \
    asm volatile("barrier.cluster.arrive.aligned;" ::: "memory"); \
    asm volatile("barrier.cluster.wait.aligned;" ::: "memory"); \
} while (0)

__global__ void __launch_bounds__(NT, 1) __cluster_dims__(CN, 1, 1)
lstm_r12_kernel(const float* __restrict__ sentence,
                const float* __restrict__ W_ih,
                const float* __restrict__ W_hh,
                const float* __restrict__ b_ih,
                const float* __restrict__ b_hh,
                const float* __restrict__ W_out,
                const float* __restrict__ b_out,
                float* __restrict__ out)
{
    __shared__ alignas(8)  unsigned long long mbar;
    __shared__ alignas(16) float hbuf[2][H_DIM];
    __shared__ alignas(16) float xbuf[CHUNK * 2];

    const int r    = threadIdx.x;     // 0..127
    const int lane = r & 31;
    const int w    = r >> 5;          // warp id
    const int sub  = lane & 7;        // h sub-index within warp
    const int grp  = lane >> 3;       // 0..3: gate id AND peer-offset group
    const uint32_t rank = cluster_rank_();

    const int hidx = (int)rank * SLICE + 8 * w + sub;  // this lane's h index
    const int gate = grp;                              // gate this lane computes
    const int gr   = gate * H_DIM + hidx;              // gate row

    // Gate-2 rows scaled by 2 (exact) so activation is uniformly sigma(y);
    // post-transform a = fma(sigma, sc, of): tanh(g) = 2*sigma(2g) - 1.
    const float scW    = (gate == 2) ? 2.0f : 1.0f;
    const float act_sc = (gate == 2) ? 2.0f : 1.0f;
    const float act_of = (gate == 2) ? -1.0f : 0.0f;

    const float wih0 = scW * W_ih[2 * gr + 0];
    const float wih1 = scW * W_ih[2 * gr + 1];
    const float br   = scW * (b_ih[gr] + b_hh[gr]);

    // W_hh row in regs, permuted: W[m] <-> h column ((32*rank + m) & 127).
    // W[0..31] = own slice, W[32..127] = remote slices in ring order.
    float W[H_DIM];
#pragma unroll
    for (int m = 0; m < H_DIM; ++m)
        W[m] = scW * W_hh[gr * H_DIM + (((int)rank * SLICE + m) & (H_DIM - 1))];

    // init
    if (r < H_DIM) { hbuf[0][r] = 0.0f; hbuf[1][r] = 0.0f; }
    const uint32_t bar_addr = smem_u32(&mbar);
    const uint32_t hb_addr  = smem_u32(&hbuf[0][0]);
    if (r == 0) mbar_init(bar_addr, N_ARRV);
    __syncthreads();
    CLUSTER_SYNC_();

    // lane-group grp targets peer CTA (rank+grp)&3; grp 0 = local
    const uint32_t peer   = (rank + (uint32_t)grp) & (CN - 1);
    const uint32_t peer_h   = mapa_u32(hb_addr,  peer);
    const uint32_t peer_bar = mapa_u32(bar_addr, peer);
    const uint32_t my_off   = (uint32_t)hidx * 4u;
    const bool is_remote    = (grp != 0);

    float c_reg = 0.0f;               // redundant across the 4 lane-groups
    float part  = 0.0f;               // own-slice partial (h(0)=0)

    for (int t0 = 0; t0 < L_SEQ; t0 += CHUNK) {
        {   // refill x chunk (2048 floats = 512 float4)
            const float4* src = (const float4*)(sentence + 2 * t0);
            float4* dst = (float4*)xbuf;
#pragma unroll
            for (int j = 0; j < 4; ++j) dst[r + j * NT] = src[r + j * NT];
        }
        __syncthreads();

#pragma unroll 1
        for (int ti = 0; ti < CHUNK; ++ti) {
            const int t = t0 + ti;

            // x-term + own partial: no hbuf dependence -> before the wait
            const float x0 = xbuf[2 * ti + 0];
            const float x1 = xbuf[2 * ti + 1];
            float acc0 = fmaf(wih0, x0, br) + part;
            float acc1 = wih1 * x1;
            float acc2 = 0.0f, acc3 = 0.0f;

            // wait for remote slices of h(t); t=0 uses zeros
            if (t != 0) mbar_wait_parity_acq_cluster(bar_addr, (uint32_t)((t - 1) & 1));

            // remote 96 cols, broadcast float4 LDS (W[32..127])
            {
                const float* hr = &hbuf[t & 1][0];
#pragma unroll
                for (int i = 1; i < CN; ++i) {
                    const uint32_t s = (rank + (uint32_t)i) & (CN - 1);
                    const float4* h4 = (const float4*)(hr + s * SLICE);
#pragma unroll
                    for (int q = 0; q < SLICE / 4; ++q) {
                        const float4 hv = h4[q];
                        acc0 = fmaf(W[SLICE * i + 4 * q + 0], hv.x, acc0);
                        acc1 = fmaf(W[SLICE * i + 4 * q + 1], hv.y, acc1);
                        acc2 = fmaf(W[SLICE * i + 4 * q + 2], hv.z, acc2);
                        acc3 = fmaf(W[SLICE * i + 4 * q + 3], hv.w, acc3);
                    }
                }
            }
            const float g = (acc0 + acc2) + (acc1 + acc3);

            // uniform activation + gate-2 post-transform (branchless)
            float a = sigmoid_f(g);
            a = fmaf(a, act_sc, act_of);

            // in-warp gate transpose: 4 shfl.idx, no smem, no barrier
            const float iv = __shfl_sync(0xffffffffu, a, sub);
            const float fv = __shfl_sync(0xffffffffu, a, sub + 8);
            const float gv = __shfl_sync(0xffffffffu, a, sub + 16);
            const float ov = __shfl_sync(0xffffffffu, a, sub + 24);

            // c/h redundantly in all 4 lane-groups (identical values)
            c_reg = fmaf(fv, c_reg, iv * gv);
            const float h = ov * tanh_f(c_reg);

            // store IMMEDIATELY, fanout parallel across lane-groups.
            // WAR-safe without extra bar: our wait at step t collected all
            // peer arrivals from step t-1, each issued after that peer
            // warp's gemv reads of buffer (t+1)&1 (shfl = warp sync).
            const int wb = (t + 1) & 1;
            if (is_remote) {
                sts_cluster_f32(peer_h + (uint32_t)(wb * H_DIM * 4) + my_off, h);
                mbar_arrive_cluster(peer_bar);
            } else {
                hbuf[wb][hidx] = h;                        // local slice
            }

            // overlap window (DSMEM in flight): publish local slice, then
            // own-slice partial of g(t+1)  (W[0..31])
            __syncthreads();                               // S2
            {
                const float4* h4 = (const float4*)(&hbuf[wb][0] + rank * SLICE);
                float p0 = 0.0f, p1 = 0.0f, p2 = 0.0f, p3 = 0.0f;
#pragma unroll
                for (int q = 0; q < SLICE / 4; ++q) {
                    const float4 hv = h4[q];
                    p0 = fmaf(W[4 * q + 0], hv.x, p0);
                    p1 = fmaf(W[4 * q + 1], hv.y, p1);
                    p2 = fmaf(W[4 * q + 2], hv.z, p2);
                    p3 = fmaf(W[4 * q + 3], hv.w, p3);
                }
                part = (p0 + p2) + (p1 + p3);
            }
        }
    }

    // final wait: collect last-step arrivals (phase (L-1)&1 = 1)
    mbar_wait_parity_acq_cluster(bar_addr, (uint32_t)((L_SEQ - 1) & 1));

    // Outputs: out[0]=sigmoid(h.W_out+b), out[1..128]=h_n, out[129..256]=c_n
    if (grp == 0) out[1 + H_DIM + hidx] = c_reg;  // 32 c values per CTA
    if (rank == 0) {
        const float* hf = &hbuf[L_SEQ & 1][0];    // = hbuf[0]
        if (r < H_DIM) out[1 + r] = hf[r];
        if (r < 32) {
            float s = 0.0f;
#pragma unroll
            for (int m = 0; m < 4; ++m)
                s = fmaf(hf[4 * r + m], W_out[4 * r + m], s);
#pragma unroll
            for (int off = 16; off > 0; off >>= 1)
                s += __shfl_xor_sync(0xffffffffu, s, off);
            if (r == 0) out[0] = sigmoid_f(s + b_out[0]);
        }
    }
    CLUSTER_SYNC_();
}

extern "C" void kernel_launch(void* const* d_in, const int* in_sizes, int n_in,
                              void* d_out, int out_size)
{
    const float* sentence = (const float*)d_in[0];
    const float* W_ih     = (const float*)d_in[1];
    const float* W_hh     = (const float*)d_in[2];
    const float* b_ih     = (const float*)d_in[3];
    const float* b_hh     = (const float*)d_in[4];
    const float* W_out    = (const float*)d_in[5];
    const float* b_out    = (const float*)d_in[6];
    float* out            = (float*)d_out;

    lstm_r12_kernel<<<CN, NT>>>(
        sentence, W_ih, W_hh, b_ih, b_hh, W_out, b_out, out);
}

// round 14
// speedup vs baseline: 1.6894x; 1.0463x over previous
#include <cuda_runtime.h>
#include <cstdint>

// LSTMTagger: 262144 sequential steps, H=128 (512 gate rows), I=2.
// R13: 8-CTA cluster (SLICE=16), 128 thr/CTA, in-warp gate transpose +
// k-split-2:
//   lane l: sub = l&3 (h sub-index), slot = l>>2 (0..7), gate = slot&3,
//   kpart = slot>>2. h-index = 16*rank + 4*warp + sub. Two threads per gate
//   row, 56 remote cols each in the main chain; combine = shfl.bfly(16),
//   then the R12 4x shfl.idx gate transpose. Gate-2 via 2*sigma(2g)-1 with
//   exactly x2-scaled weights (branchless).
//   Store fanout: slot s -> peer (rank+s)&7 (slot 0 local), 1 st + 1 PLAIN
//   arrive per lane (R11 finding: explicit .release costs ~190cyc/step).
//   8 own cols per thread computed in the S2 overlap window (DSMEM flight).
// Full fp32, __expf activations. Double-buffered h.

#define L_SEQ   262144
#define H_DIM   128
#define SLICE   16
#define CN      8
#define NT      128
#define CHUNK   1024
#define RCOLS   56      // remote cols per thread (112/2)
#define OCOLS   8       // own cols per thread (16/2)
#define N_ARRV  112     // 7 peers x 16 lanes per phase

__device__ __forceinline__ float sigmoid_f(float x) {
    return __fdividef(1.0f, 1.0f + __expf(-x));
}
__device__ __forceinline__ float tanh_f(float x) {
    return 1.0f - __fdividef(2.0f, 1.0f + __expf(2.0f * x));
}

__device__ __forceinline__ uint32_t smem_u32(const void* ptr) {
    uint32_t a;
    asm("{ .reg .u64 t; cvta.to.shared.u64 t, %1; cvt.u32.u64 %0, t; }"
        : "=r"(a) : "l"(ptr));
    return a;
}
__device__ __forceinline__ uint32_t cluster_rank_() {
    uint32_t v; asm("mov.u32 %0, %%cluster_ctarank;" : "=r"(v)); return v;
}
__device__ __forceinline__ uint32_t mapa_u32(uint32_t addr, uint32_t rk) {
    uint32_t v;
    asm("mapa.shared::cluster.u32 %0, %1, %2;" : "=r"(v) : "r"(addr), "r"(rk));
    return v;
}
__device__ __forceinline__ void sts_cluster_f32(uint32_t raddr, float v) {
    asm volatile("st.shared::cluster.f32 [%0], %1;"
                 :: "r"(raddr), "f"(v) : "memory");
}
__device__ __forceinline__ void mbar_arrive_cluster(uint32_t raddr) {
    asm volatile("mbarrier.arrive.shared::cluster.b64 _, [%0];"
                 :: "r"(raddr) : "memory");
}
__device__ __forceinline__ void mbar_init(uint32_t addr, uint32_t count) {
    asm volatile("mbarrier.init.shared.b64 [%0], %1;"
                 :: "r"(addr), "r"(count) : "memory");
}
__device__ __forceinline__ void mbar_wait_parity_acq_cluster(uint32_t addr,
                                                             uint32_t parity) {
    uint32_t done;
    asm volatile(
        "{\n\t.reg .pred p;\n\t"
        "mbarrier.try_wait.parity.acquire.cluster.shared::cta.b64 p, [%1], %2;\n\t"
        "selp.b32 %0, 1, 0, p;\n\t}"
        : "=r"(done) : "r"(addr), "r"(parity) : "memory");
    if (!done) {
        asm volatile(
            "{\n\t.reg .pred P1;\n\t"
            "WL_%=:\n\t"
            "mbarrier.try_wait.parity.acquire.cluster.shared::cta.b64 P1, [%0], %1, 0x989680;\n\t"
            "@P1 bra.uni WD_%=;\n\t"
            "bra.uni WL_%=;\n\t"
            "WD_%=:\n\t}"
            :: "r"(addr), "r"(parity) : "memory");
    }
}
#define CLUSTER_SYNC_() do { \
    asm volatile("barrier.cluster.arrive.aligned;" ::: "memory"); \
    asm volatile("barrier.cluster.wait.aligned;" ::: "memory"); \
} while (0)

__global__ void __launch_bounds__(NT, 1) __cluster_dims__(CN, 1, 1)
lstm_r13_kernel(const float* __restrict__ sentence,
                const float* __restrict__ W_ih,
                const float* __restrict__ W_hh,
                const float* __restrict__ b_ih,
                const float* __restrict__ b_hh,
                const float* __restrict__ W_out,
                const float* __restrict__ b_out,
                float* __restrict__ out)
{
    __shared__ alignas(8)  unsigned long long mbar;
    __shared__ alignas(16) float hbuf[2][H_DIM];
    __shared__ alignas(16) float xbuf[CHUNK * 2];

    const int r     = threadIdx.x;    // 0..127
    const int lane  = r & 31;
    const int w     = r >> 5;         // warp id 0..3
    const int sub   = lane & 3;       // h sub-index within warp
    const int slot  = lane >> 2;      // 0..7: (gate, kpart) AND peer group
    const int gate  = slot & 3;
    const int kpart = slot >> 2;      // 0 or 1
    const uint32_t rank = cluster_rank_();

    const int hidx = (int)rank * SLICE + 4 * w + sub;  // this lane's h index
    const int gr   = gate * H_DIM + hidx;              // gate row

    // Gate-2 rows scaled by 2 (exact): tanh(g) = 2*sigma(2g) - 1.
    const float scW    = (gate == 2) ? 2.0f : 1.0f;
    const float act_sc = (gate == 2) ? 2.0f : 1.0f;
    const float act_of = (gate == 2) ? -1.0f : 0.0f;

    // Affine term only on kpart 0 (k-combine sums the two halves).
    const float wih0 = (kpart == 0) ? scW * W_ih[2 * gr + 0] : 0.0f;
    const float wih1 = (kpart == 0) ? scW * W_ih[2 * gr + 1] : 0.0f;
    const float br   = (kpart == 0) ? scW * (b_ih[gr] + b_hh[gr]) : 0.0f;

    // Column windows (actual h column = permuted index & 127):
    //   remote: KBASE + jj, jj in [0,56)   KBASE = 16*rank + 16 + kpart*56
    //   own:    OWNB  + j,  j  in [0,8)    OWNB  = 16*rank + kpart*8
    const int KBASE = (int)rank * SLICE + SLICE + kpart * RCOLS;
    const int OWNB  = (int)rank * SLICE + kpart * OCOLS;

    float Wr[RCOLS], Wo[OCOLS];
    {
        const float* wrow = W_hh + gr * H_DIM;
#pragma unroll
        for (int jj = 0; jj < RCOLS; ++jj)
            Wr[jj] = scW * wrow[(KBASE + jj) & (H_DIM - 1)];
#pragma unroll
        for (int j = 0; j < OCOLS; ++j)
            Wo[j] = scW * wrow[OWNB + j];
    }

    // init
    if (r < H_DIM) { hbuf[0][r] = 0.0f; hbuf[1][r] = 0.0f; }
    const uint32_t bar_addr = smem_u32(&mbar);
    const uint32_t hb_addr  = smem_u32(&hbuf[0][0]);
    if (r == 0) mbar_init(bar_addr, N_ARRV);
    __syncthreads();
    CLUSTER_SYNC_();

    // slot s targets peer CTA (rank+s)&7; slot 0 = local
    const uint32_t peer     = (rank + (uint32_t)slot) & (CN - 1);
    const uint32_t peer_h   = mapa_u32(hb_addr,  peer);
    const uint32_t peer_bar = mapa_u32(bar_addr, peer);
    const uint32_t my_off   = (uint32_t)hidx * 4u;
    const bool is_remote    = (slot != 0);

    float c_reg = 0.0f;               // redundant across the 8 slots
    float part  = 0.0f;               // own-half partial (h(0)=0)

    for (int t0 = 0; t0 < L_SEQ; t0 += CHUNK) {
        {   // refill x chunk (2048 floats = 512 float4)
            const float4* src = (const float4*)(sentence + 2 * t0);
            float4* dst = (float4*)xbuf;
#pragma unroll
            for (int j = 0; j < 4; ++j) dst[r + j * NT] = src[r + j * NT];
        }
        __syncthreads();

#pragma unroll 1
        for (int ti = 0; ti < CHUNK; ++ti) {
            const int t = t0 + ti;

            // affine + own partial before the wait (no hbuf dependence)
            const float x0 = xbuf[2 * ti + 0];
            const float x1 = xbuf[2 * ti + 1];
            float acc0 = fmaf(wih0, x0, br) + part;
            float acc1 = wih1 * x1;
            float acc2 = 0.0f, acc3 = 0.0f;

            // wait for remote slices of h(t); t=0 uses zeros
            if (t != 0) mbar_wait_parity_acq_cluster(bar_addr, (uint32_t)((t - 1) & 1));

            // remote 56 cols: 14 aligned float4 groups (KBASE % 4 == 0,
            // groups never straddle the &127 wrap)
            {
                const float* hr = &hbuf[t & 1][0];
#pragma unroll
                for (int q = 0; q < RCOLS / 4; ++q) {
                    const int col = (KBASE + 4 * q) & (H_DIM - 1);
                    const float4 hv = *(const float4*)(hr + col);
                    acc0 = fmaf(Wr[4 * q + 0], hv.x, acc0);
                    acc1 = fmaf(Wr[4 * q + 1], hv.y, acc1);
                    acc2 = fmaf(Wr[4 * q + 2], hv.z, acc2);
                    acc3 = fmaf(Wr[4 * q + 3], hv.w, acc3);
                }
            }
            float s = (acc0 + acc2) + (acc1 + acc3);

            // k-combine: lanes l and l^16 are same gate/sub, different kpart
            s += __shfl_xor_sync(0xffffffffu, s, 16);

            // uniform activation + gate-2 post-transform (branchless)
            float a = sigmoid_f(s);
            a = fmaf(a, act_sc, act_of);

            // gate transpose: gate g's value lives at lane 4*g + sub
            const float iv = __shfl_sync(0xffffffffu, a, sub);
            const float fv = __shfl_sync(0xffffffffu, a, 4 + sub);
            const float gv = __shfl_sync(0xffffffffu, a, 8 + sub);
            const float ov = __shfl_sync(0xffffffffu, a, 12 + sub);

            // c/h redundantly in all 8 slots (identical values)
            c_reg = fmaf(fv, c_reg, iv * gv);
            const float h = ov * tanh_f(c_reg);

            // store IMMEDIATELY, fanout parallel across slots. WAR-safe:
            // every peer's next-step wait collects arrivals from all 4 of
            // our warps, each issued after that warp's reads (shfl-synced).
            const int wb = (t + 1) & 1;
            if (is_remote) {
                sts_cluster_f32(peer_h + (uint32_t)(wb * H_DIM * 4) + my_off, h);
                mbar_arrive_cluster(peer_bar);
            } else {
                hbuf[wb][hidx] = h;                        // local slice
            }

            // overlap window (DSMEM in flight): publish local slice, then
            // own-half partial of g(t+1)
            __syncthreads();                               // S2
            {
                const float4* h4 = (const float4*)(&hbuf[wb][OWNB]);
                float p0 = 0.0f, p1 = 0.0f, p2 = 0.0f, p3 = 0.0f;
#pragma unroll
                for (int q = 0; q < OCOLS / 4; ++q) {
                    const float4 hv = h4[q];
                    p0 = fmaf(Wo[4 * q + 0], hv.x, p0);
                    p1 = fmaf(Wo[4 * q + 1], hv.y, p1);
                    p2 = fmaf(Wo[4 * q + 2], hv.z, p2);
                    p3 = fmaf(Wo[4 * q + 3], hv.w, p3);
                }
                part = (p0 + p2) + (p1 + p3);
            }
        }
    }

    // final wait: collect last-step arrivals (phase (L-1)&1 = 1)
    mbar_wait_parity_acq_cluster(bar_addr, (uint32_t)((L_SEQ - 1) & 1));

    // Outputs: out[0]=sigmoid(h.W_out+b), out[1..128]=h_n, out[129..256]=c_n
    if (slot == 0) out[1 + H_DIM + hidx] = c_reg;  // 16 c values per CTA
    if (rank == 0) {
        const float* hf = &hbuf[L_SEQ & 1][0];     // = hbuf[0]
        if (r < H_DIM) out[1 + r] = hf[r];
        if (r < 32) {
            float s = 0.0f;
#pragma unroll
            for (int m = 0; m < 4; ++m)
                s = fmaf(hf[4 * r + m], W_out[4 * r + m], s);
#pragma unroll
            for (int off = 16; off > 0; off >>= 1)
                s += __shfl_xor_sync(0xffffffffu, s, off);
            if (r == 0) out[0] = sigmoid_f(s + b_out[0]);
        }
    }
    CLUSTER_SYNC_();
}

extern "C" void kernel_launch(void* const* d_in, const int* in_sizes, int n_in,
                              void* d_out, int out_size)
{
    const float* sentence = (const float*)d_in[0];
    const float* W_ih     = (const float*)d_in[1];
    const float* W_hh     = (const float*)d_in[2];
    const float* b_ih     = (const float*)d_in[3];
    const float* b_hh     = (const float*)d_in[4];
    const float* W_out    = (const float*)d_in[5];
    const float* b_out    = (const float*)d_in[6];
    float* out            = (float*)d_out;

    lstm_r13_kernel<<<CN, NT>>>(
        sentence, W_ih, W_hh, b_ih, b_hh, W_out, b_out, out);
}